// round 14
// baseline (speedup 1.0000x reference)
#include <cuda_runtime.h>
#include <cuda_fp16.h>
#include <cstdint>
#include <math.h>

// ---------------- problem constants ----------------
#define NN 50000        // nodes
#define EE 1600000      // edges
#define FD 48           // out dim
#define HD 256          // hidden / in dim
#define KHOP 10
#define SCAN_BLOCKS ((NN + 1023) / 1024)   // 49

// ---------------- device scratch ----------------
__device__ int    g_is64;
__device__ int    g_deg[NN];
__device__ float  g_dinv[NN];
__device__ int    g_offs[NN + 1];
__device__ int    g_cursor[NN];
__device__ int    g_bsum[64];
__device__ int    g_bsumx[64];
__device__ int2   g_cw[EE];                    // packed (col, weight-bits)
__device__ float  g_h1[(size_t)NN * HD];       // relu(x@W1+b1)
__device__ __half g_hk0h[(size_t)NN * FD];     // propagated state (fp16)
__device__ __half g_hk1h[(size_t)NN * FD];
__device__ float  g_hidden[(size_t)NN * FD];   // fp32 accumulator

// ---------------- helpers ----------------
__device__ __forceinline__ unsigned tf32_bits(float x) {
    unsigned u;
    asm("cvt.rna.tf32.f32 %0, %1;" : "=r"(u) : "f"(x));
    return u;
}
__device__ __forceinline__ void cp_async16(uint32_t smem, const void* gptr, bool valid) {
    int sz = valid ? 16 : 0;
    asm volatile("cp.async.ca.shared.global [%0], [%1], 16, %2;\n"
                 :: "r"(smem), "l"(gptr), "r"(sz));
}
__device__ __forceinline__ void cp_async_commit() {
    asm volatile("cp.async.commit_group;\n");
}
template <int N>
__device__ __forceinline__ void cp_async_wait() {
    asm volatile("cp.async.wait_group %0;\n" :: "n"(N));
}

// ---------------- detect edge dtype + init degrees --------------------------
__global__ void detect_init_kernel(const void* ei) {
    int i = blockIdx.x * blockDim.x + threadIdx.x;
    if (i < NN) g_deg[i] = 1;
    if (i == 0) {
        const long long* p = (const long long*)ei;
        int ok = 1;
        for (int j = 0; j < 64; j++) {
            long long v = p[j];
            if (v < 0 || v >= NN) { ok = 0; break; }
        }
        g_is64 = ok;
    }
}

// histogram dst
__global__ void count_kernel(const void* ei) {
    int e = blockIdx.x * blockDim.x + threadIdx.x;
    if (e >= EE) return;
    int d;
    if (g_is64) {
        const long long* p = (const long long*)ei;
        d = (int)p[(size_t)EE + e];
    } else {
        const int* p = (const int*)ei;
        d = p[EE + e];
    }
    atomicAdd(&g_deg[d], 1);
}

// ---------------- 3-phase scan over (deg-1); also dinv ----------------------
__global__ void scan_block_kernel() {          // SCAN_BLOCKS x 1024
    int i = blockIdx.x * 1024 + threadIdx.x;
    int deg = (i < NN) ? g_deg[i] : 1;
    int v = deg - 1;
    if (i < NN) g_dinv[i] = rsqrtf((float)deg);
    int lane = threadIdx.x & 31;
    int wid  = threadIdx.x >> 5;
    int x = v;
#pragma unroll
    for (int o = 1; o < 32; o <<= 1) {
        int y = __shfl_up_sync(0xffffffffu, x, o);
        if (lane >= o) x += y;
    }
    __shared__ int ws[32];
    if (lane == 31) ws[wid] = x;
    __syncthreads();
    if (wid == 0) {
        int w = ws[lane];
#pragma unroll
        for (int o = 1; o < 32; o <<= 1) {
            int y = __shfl_up_sync(0xffffffffu, w, o);
            if (lane >= o) w += y;
        }
        ws[lane] = w;
    }
    __syncthreads();
    int incl = x + (wid > 0 ? ws[wid - 1] : 0);
    if (i < NN) g_offs[i] = incl - v;          // block-local exclusive
    if (threadIdx.x == 1023) g_bsum[blockIdx.x] = incl;  // block total
}

__global__ void scan_sums_kernel() {           // 1 block x 64
    int lane = threadIdx.x & 31;
    int wid  = threadIdx.x >> 5;
    int v = (threadIdx.x < SCAN_BLOCKS) ? g_bsum[threadIdx.x] : 0;
    int x = v;
#pragma unroll
    for (int o = 1; o < 32; o <<= 1) {
        int y = __shfl_up_sync(0xffffffffu, x, o);
        if (lane >= o) x += y;
    }
    __shared__ int ws[2];
    if (lane == 31) ws[wid] = x;
    __syncthreads();
    int incl = x + (wid > 0 ? ws[0] : 0);
    if (threadIdx.x < SCAN_BLOCKS) g_bsumx[threadIdx.x] = incl - v; // exclusive
    if (threadIdx.x == 63) g_offs[NN] = incl;  // grand total (E)
}

__global__ void scan_add_kernel() {            // SCAN_BLOCKS x 1024
    int i = blockIdx.x * 1024 + threadIdx.x;
    if (i >= NN) return;
    int e = g_offs[i] + g_bsumx[blockIdx.x];
    g_offs[i] = e;
    g_cursor[i] = e;
}

// ---------------- SGEMM1 (tf32 TC + cp.async double-buffer) -----------------
// h1 = relu(x@W1+b1). BK=16, two smem buffers; raw fp32 bits fed to mma.tf32
// (HW truncates to tf32 — no cvt pass). A-stride 20 floats: conflict-free
// A-fragment LDS; B-stride 132 as before.
#define A1S 20      // floats per A row (16 + 4 pad), 80B (16B aligned)
#define B1S 132     // floats per B row
#define NTILE (HD / 16)   // 16 tiles

__global__ void __launch_bounds__(256, 2)
sgemm1_tc_kernel(const float* __restrict__ A,
                 const float* __restrict__ B,
                 const float* __restrict__ bias) {
    __shared__ float As[2][128 * A1S];
    __shared__ float Bs[2][16 * B1S];
    int tid  = threadIdx.x;
    int warp = tid >> 5;
    int lane = tid & 31;
    int g = lane >> 2;
    int t = lane & 3;
    int wm = (warp & 3) * 32;
    int wn = (warp >> 2) * 64;
    int bm = blockIdx.y * 128;
    int bn = blockIdx.x * 128;

    // per-thread copy slots: A tile = 512 16B chunks, B tile = 512 chunks
    int ar0 = tid >> 1;             // A chunk i=0: row, f
    int af0 = (tid & 1) * 2;        // f in {0,2} then +1 => handles 2 chunks
    // simpler: chunk id c = tid + i*256; row=c>>2, f=c&3
    float c[2][8][4];
#pragma unroll
    for (int mt = 0; mt < 2; mt++)
#pragma unroll
        for (int nt = 0; nt < 8; nt++)
#pragma unroll
            for (int i = 0; i < 4; i++) c[mt][nt][i] = 0.f;

    uint32_t as_base0 = (uint32_t)__cvta_generic_to_shared(&As[0][0]);
    uint32_t as_base1 = (uint32_t)__cvta_generic_to_shared(&As[1][0]);
    uint32_t bs_base0 = (uint32_t)__cvta_generic_to_shared(&Bs[0][0]);
    uint32_t bs_base1 = (uint32_t)__cvta_generic_to_shared(&Bs[1][0]);

    // issue copy of tile `ti` into buffer `buf`
    auto issue_tile = [&](int ti, int buf) {
        int k0 = ti * 16;
        uint32_t asb = buf ? as_base1 : as_base0;
        uint32_t bsb = buf ? bs_base1 : bs_base0;
#pragma unroll
        for (int i = 0; i < 2; i++) {
            int cid = tid + i * 256;
            int row = cid >> 2;           // 0..127
            int f   = cid & 3;            // 0..3
            bool v = (bm + row) < NN;
            const float* src = &A[(size_t)(bm + row) * HD + k0 + f * 4];
            cp_async16(asb + (row * A1S + f * 4) * 4, src, v);
        }
#pragma unroll
        for (int i = 0; i < 2; i++) {
            int cid = tid + i * 256;
            int row = cid >> 5;           // 0..15
            int f   = cid & 31;           // 0..31
            const float* src = &B[(size_t)(k0 + row) * 256 + bn + f * 4];
            cp_async16(bsb + (row * B1S + f * 4) * 4, src, true);
        }
        cp_async_commit();
    };

    issue_tile(0, 0);

    for (int ti = 0; ti < NTILE; ti++) {
        int buf = ti & 1;
        if (ti + 1 < NTILE) {
            issue_tile(ti + 1, buf ^ 1);
            cp_async_wait<1>();
        } else {
            cp_async_wait<0>();
        }
        __syncthreads();

        const float* Asb = As[buf];
        const float* Bsb = Bs[buf];
#pragma unroll
        for (int kk = 0; kk < 16; kk += 8) {
            unsigned a[2][4];
#pragma unroll
            for (int mt = 0; mt < 2; mt++) {
                int mrow = wm + mt * 16;
                a[mt][0] = __float_as_uint(Asb[(mrow + g)     * A1S + kk + t]);
                a[mt][1] = __float_as_uint(Asb[(mrow + g + 8) * A1S + kk + t]);
                a[mt][2] = __float_as_uint(Asb[(mrow + g)     * A1S + kk + t + 4]);
                a[mt][3] = __float_as_uint(Asb[(mrow + g + 8) * A1S + kk + t + 4]);
            }
            unsigned b[8][2];
#pragma unroll
            for (int nt = 0; nt < 8; nt++) {
                int ncol = wn + nt * 8;
                b[nt][0] = __float_as_uint(Bsb[(kk + t)     * B1S + ncol + g]);
                b[nt][1] = __float_as_uint(Bsb[(kk + t + 4) * B1S + ncol + g]);
            }
#pragma unroll
            for (int mt = 0; mt < 2; mt++)
#pragma unroll
                for (int nt = 0; nt < 8; nt++) {
                    asm volatile(
                        "mma.sync.aligned.m16n8k8.row.col.f32.tf32.tf32.f32 "
                        "{%0,%1,%2,%3}, {%4,%5,%6,%7}, {%8,%9}, {%0,%1,%2,%3};"
                        : "+f"(c[mt][nt][0]), "+f"(c[mt][nt][1]),
                          "+f"(c[mt][nt][2]), "+f"(c[mt][nt][3])
                        : "r"(a[mt][0]), "r"(a[mt][1]), "r"(a[mt][2]), "r"(a[mt][3]),
                          "r"(b[nt][0]), "r"(b[nt][1]));
                }
        }
        __syncthreads();   // before buffer is overwritten two iterations later
    }

    // epilogue: bias + relu
#pragma unroll
    for (int mt = 0; mt < 2; mt++) {
        int row0 = bm + wm + mt * 16 + g;
        int row1 = row0 + 8;
#pragma unroll
        for (int nt = 0; nt < 8; nt++) {
            int col = bn + wn + nt * 8 + 2 * t;
            float bsv0 = bias[col];
            float bsv1 = bias[col + 1];
            if (row0 < NN) {
                float v0 = c[mt][nt][0] + bsv0;
                float v1 = c[mt][nt][1] + bsv1;
                g_h1[(size_t)row0 * HD + col]     = v0 > 0.f ? v0 : 0.f;
                g_h1[(size_t)row0 * HD + col + 1] = v1 > 0.f ? v1 : 0.f;
            }
            if (row1 < NN) {
                float v2 = c[mt][nt][2] + bsv0;
                float v3 = c[mt][nt][3] + bsv1;
                g_h1[(size_t)row1 * HD + col]     = v2 > 0.f ? v2 : 0.f;
                g_h1[(size_t)row1 * HD + col + 1] = v3 > 0.f ? v3 : 0.f;
            }
        }
    }
    (void)ar0; (void)af0;
}

// ---------------- scatter into CSR straight from edge_index -----------------
__global__ void scatter_kernel(const void* ei) {
    int e = blockIdx.x * blockDim.x + threadIdx.x;
    if (e >= EE) return;
    int s, d;
    if (g_is64) {
        const long long* p = (const long long*)ei;
        s = (int)p[e];
        d = (int)p[(size_t)EE + e];
    } else {
        const int* p = (const int*)ei;
        s = p[e];
        d = p[EE + e];
    }
    int pos = atomicAdd(&g_cursor[d], 1);
    float w = g_dinv[s] * g_dinv[d];
    g_cw[pos] = make_int2(s, __float_as_int(w));
}

// ---------------- SGEMM2 (tf32 tensor cores) --------------------------------
#define A2_STRIDE 40
#define B2_STRIDE 52

__global__ void __launch_bounds__(256, 2)
sgemm2_tc_kernel(const float* __restrict__ B,     // W2 [256,48]
                 const float* __restrict__ bias,  // b2 [48]
                 const float* __restrict__ temp) {
    __shared__ float As[128 * A2_STRIDE];
    __shared__ float Bs[32 * B2_STRIDE];
    int tid  = threadIdx.x;
    int warp = tid >> 5;
    int lane = tid & 31;
    int g = lane >> 2;
    int t = lane & 3;
    int wm = warp * 16;
    int bm = blockIdx.x * 128;

    float c[6][4];
#pragma unroll
    for (int nt = 0; nt < 6; nt++)
#pragma unroll
        for (int i = 0; i < 4; i++) c[nt][i] = 0.f;

    for (int k0 = 0; k0 < HD; k0 += 32) {
#pragma unroll
        for (int i = 0; i < 4; i++) {
            int idx = tid + i * 256;
            int row = idx >> 3;
            int f   = idx & 7;
            float4 v;
            if (bm + row < NN)
                v = *(const float4*)&g_h1[(size_t)(bm + row) * HD + k0 + f * 4];
            else
                v = make_float4(0.f, 0.f, 0.f, 0.f);
            *(float4*)&As[row * A2_STRIDE + f * 4] = v;
        }
        for (int idx = tid; idx < 384; idx += 256) {
            int row = idx / 12;
            int f   = idx - row * 12;
            float4 v = *(const float4*)&B[(size_t)(k0 + row) * 48 + f * 4];
            *(float4*)&Bs[row * B2_STRIDE + f * 4] = v;
        }
        __syncthreads();

#pragma unroll
        for (int kk = 0; kk < 32; kk += 8) {
            unsigned a[4];
            a[0] = __float_as_uint(As[(wm + g)     * A2_STRIDE + kk + t]);
            a[1] = __float_as_uint(As[(wm + g + 8) * A2_STRIDE + kk + t]);
            a[2] = __float_as_uint(As[(wm + g)     * A2_STRIDE + kk + t + 4]);
            a[3] = __float_as_uint(As[(wm + g + 8) * A2_STRIDE + kk + t + 4]);
            unsigned b[6][2];
#pragma unroll
            for (int nt = 0; nt < 6; nt++) {
                int ncol = nt * 8;
                b[nt][0] = __float_as_uint(Bs[(kk + t)     * B2_STRIDE + ncol + g]);
                b[nt][1] = __float_as_uint(Bs[(kk + t + 4) * B2_STRIDE + ncol + g]);
            }
#pragma unroll
            for (int nt = 0; nt < 6; nt++) {
                asm volatile(
                    "mma.sync.aligned.m16n8k8.row.col.f32.tf32.tf32.f32 "
                    "{%0,%1,%2,%3}, {%4,%5,%6,%7}, {%8,%9}, {%0,%1,%2,%3};"
                    : "+f"(c[nt][0]), "+f"(c[nt][1]),
                      "+f"(c[nt][2]), "+f"(c[nt][3])
                    : "r"(a[0]), "r"(a[1]), "r"(a[2]), "r"(a[3]),
                      "r"(b[nt][0]), "r"(b[nt][1]));
            }
        }
        __syncthreads();
    }

    float t0 = temp[0];
    int row0 = bm + wm + g;
    int row1 = row0 + 8;
#pragma unroll
    for (int nt = 0; nt < 6; nt++) {
        int col = nt * 8 + 2 * t;
        float bs0 = bias[col];
        float bs1 = bias[col + 1];
        if (row0 < NN) {
            float v0 = c[nt][0] + bs0;
            float v1 = c[nt][1] + bs1;
            size_t o = (size_t)row0 * FD + col;
            g_hk0h[o]     = __float2half(v0);
            g_hk0h[o + 1] = __float2half(v1);
            g_hidden[o]     = t0 * v0;
            g_hidden[o + 1] = t0 * v1;
        }
        if (row1 < NN) {
            float v2 = c[nt][2] + bs0;
            float v3 = c[nt][3] + bs1;
            size_t o = (size_t)row1 * FD + col;
            g_hk0h[o]     = __float2half(v2);
            g_hk0h[o + 1] = __float2half(v3);
            g_hidden[o]     = t0 * v2;
            g_hidden[o + 1] = t0 * v3;
        }
    }
}

// ---------------- SpMM hop (fp16 state, 12 threads/node, 16-edge unroll) ----
#define SPMM_EDGE(ci, vi)                                                     \
    do {                                                                      \
        float w_ = __int_as_float((ci).y);                                    \
        float2 f_;                                                            \
        f_ = __half22float2(*(__half2*)&(vi).x); a0 += w_ * f_.x; a1 += w_ * f_.y; \
        f_ = __half22float2(*(__half2*)&(vi).y); a2 += w_ * f_.x; a3 += w_ * f_.y; \
    } while (0)

__global__ void spmm_kernel(const float* __restrict__ temp, int k, int parity,
                            int store_next) {
    const __half* curh = parity ? g_hk1h : g_hk0h;
    __half*       nxth = parity ? g_hk0h : g_hk1h;
    int t = blockIdx.x * blockDim.x + threadIdx.x;
    if (t >= NN * 12) return;
    int d = t / 12;
    int q = t - d * 12;
    const uint2* __restrict__ curv = (const uint2*)curh;

    int e0 = g_offs[d];
    int e1 = g_offs[d + 1];
    float a0 = 0.f, a1 = 0.f, a2 = 0.f, a3 = 0.f;

    int e = e0;
    for (; e + 16 <= e1; e += 16) {
        int2  cc[16];
        uint2 vv[16];
#pragma unroll
        for (int j = 0; j < 16; j++) cc[j] = g_cw[e + j];
#pragma unroll
        for (int j = 0; j < 16; j++) vv[j] = __ldg(&curv[cc[j].x * 12 + q]);
#pragma unroll
        for (int j = 0; j < 16; j++) SPMM_EDGE(cc[j], vv[j]);
    }
    for (; e + 4 <= e1; e += 4) {
        int2 c0 = g_cw[e + 0];
        int2 c1 = g_cw[e + 1];
        int2 c2 = g_cw[e + 2];
        int2 c3 = g_cw[e + 3];
        uint2 v0 = __ldg(&curv[c0.x * 12 + q]);
        uint2 v1 = __ldg(&curv[c1.x * 12 + q]);
        uint2 v2 = __ldg(&curv[c2.x * 12 + q]);
        uint2 v3 = __ldg(&curv[c3.x * 12 + q]);
        SPMM_EDGE(c0, v0); SPMM_EDGE(c1, v1);
        SPMM_EDGE(c2, v2); SPMM_EDGE(c3, v3);
    }
    for (; e < e1; e++) {
        int2 c0 = g_cw[e];
        uint2 v0 = __ldg(&curv[c0.x * 12 + q]);
        SPMM_EDGE(c0, v0);
    }
    // self loop
    {
        float di = g_dinv[d];
        float sw = di * di;
        uint2 v0 = __ldg(&curv[d * 12 + q]);
        float2 f;
        f = __half22float2(*(__half2*)&v0.x); a0 += sw * f.x; a1 += sw * f.y;
        f = __half22float2(*(__half2*)&v0.y); a2 += sw * f.x; a3 += sw * f.y;
    }

    float tk = temp[k];
    if (store_next) {
        uint2 packed;
        __half2 h0 = __floats2half2_rn(a0, a1);
        __half2 h1 = __floats2half2_rn(a2, a3);
        packed.x = *(unsigned*)&h0;
        packed.y = *(unsigned*)&h1;
        ((uint2*)nxth)[t] = packed;
    }
    float4* hidv = (float4*)g_hidden;
    float4 hv = hidv[t];
    hv.x += tk * a0; hv.y += tk * a1;
    hv.z += tk * a2; hv.w += tk * a3;
    hidv[t] = hv;
}

// ---------------- log_softmax over 48 cols, warp per row --------------------
__global__ void logsoftmax_kernel(float* __restrict__ out) {
    int warp = (blockIdx.x * blockDim.x + threadIdx.x) >> 5;
    int lane = threadIdx.x & 31;
    if (warp >= NN) return;
    size_t base = (size_t)warp * FD;
    float v0 = g_hidden[base + lane];
    float v1 = (lane < 16) ? g_hidden[base + 32 + lane] : -INFINITY;
    float m = fmaxf(v0, v1);
#pragma unroll
    for (int off = 16; off > 0; off >>= 1)
        m = fmaxf(m, __shfl_xor_sync(0xffffffffu, m, off));
    float s = expf(v0 - m) + ((lane < 16) ? expf(v1 - m) : 0.f);
#pragma unroll
    for (int off = 16; off > 0; off >>= 1)
        s += __shfl_xor_sync(0xffffffffu, s, off);
    float l = m + logf(s);
    out[base + lane] = v0 - l;
    if (lane < 16) out[base + 32 + lane] = v1 - l;
}

// ---------------- launch (fork CSR build onto side stream) ------------------
extern "C" void kernel_launch(void* const* d_in, const int* in_sizes, int n_in,
                              void* d_out, int out_size) {
    const float* x    = (const float*)d_in[0];
    const void*  ei   = d_in[1];
    const float* W1   = (const float*)d_in[2];
    const float* b1   = (const float*)d_in[3];
    const float* W2   = (const float*)d_in[4];
    const float* b2   = (const float*)d_in[5];
    const float* temp = (const float*)d_in[6];
    float* out = (float*)d_out;

    static cudaStream_t s2 = nullptr;
    static cudaEvent_t ev_fork = nullptr, ev_join = nullptr;
    if (s2 == nullptr) {
        cudaStreamCreateWithFlags(&s2, cudaStreamNonBlocking);
        cudaEventCreateWithFlags(&ev_fork, cudaEventDisableTiming);
        cudaEventCreateWithFlags(&ev_join, cudaEventDisableTiming);
    }

    // fork: side stream builds CSR while main stream runs the MLP GEMMs
    cudaEventRecord(ev_fork, 0);
    cudaStreamWaitEvent(s2, ev_fork, 0);

    detect_init_kernel<<<(NN + 255) / 256, 256, 0, s2>>>(ei);
    count_kernel<<<(EE + 255) / 256, 256, 0, s2>>>(ei);
    scan_block_kernel<<<SCAN_BLOCKS, 1024, 0, s2>>>();
    scan_sums_kernel<<<1, 64, 0, s2>>>();
    scan_add_kernel<<<SCAN_BLOCKS, 1024, 0, s2>>>();
    scatter_kernel<<<(EE + 255) / 256, 256, 0, s2>>>(ei);
    cudaEventRecord(ev_join, s2);

    dim3 g1(2, (NN + 127) / 128);
    sgemm1_tc_kernel<<<g1, 256>>>(x, W1, b1);
    sgemm2_tc_kernel<<<(NN + 127) / 128, 256>>>(W2, b2, temp);

    // join: spmm needs CSR (side) and hk0/hidden (main)
    cudaStreamWaitEvent(0, ev_join, 0);

    int spmm_threads = NN * 12;
    int spmm_blocks = (spmm_threads + 255) / 256;
    for (int k = 1; k <= KHOP; k++) {
        spmm_kernel<<<spmm_blocks, 256>>>(temp, k, (k - 1) & 1, k < KHOP);
    }
    logsoftmax_kernel<<<(NN * 32 + 255) / 256, 256>>>(out);
}

// round 16
// speedup vs baseline: 1.0174x; 1.0174x over previous
#include <cuda_runtime.h>
#include <cuda_fp16.h>
#include <cstdint>
#include <math.h>

// ---------------- problem constants ----------------
#define NN 50000        // nodes
#define EE 1600000      // edges
#define FD 48           // out dim
#define HD 256          // hidden / in dim
#define KHOP 10
#define SCAN_BLOCKS ((NN + 1023) / 1024)   // 49
#define SPMM_NODES 32                      // nodes per block
#define SPMM_THREADS (SPMM_NODES * 12)     // 384
#define SPMM_CHUNK 2048                    // staged edges (16KB smem)

// ---------------- device scratch ----------------
__device__ int    g_is64;
__device__ int    g_deg[NN];
__device__ float  g_dinv[NN];
__device__ int    g_offs[NN + 1];
__device__ int    g_cursor[NN];
__device__ int    g_bsum[64];
__device__ int    g_bsumx[64];
__device__ int2   g_cw[EE];                    // packed (col, weight-bits)
__device__ float  g_h1[(size_t)NN * HD];       // relu(x@W1+b1)
__device__ __half g_hk0h[(size_t)NN * FD];     // propagated state (fp16)
__device__ __half g_hk1h[(size_t)NN * FD];
__device__ float  g_hidden[(size_t)NN * FD];   // fp32 accumulator

// ---------------- helpers ----------------
__device__ __forceinline__ unsigned tf32_bits(float x) {
    unsigned u;
    asm("cvt.rna.tf32.f32 %0, %1;" : "=r"(u) : "f"(x));
    return u;
}

// ---------------- detect edge dtype + init degrees --------------------------
__global__ void detect_init_kernel(const void* ei) {
    int i = blockIdx.x * blockDim.x + threadIdx.x;
    if (i < NN) g_deg[i] = 1;
    if (i == 0) {
        const long long* p = (const long long*)ei;
        int ok = 1;
        for (int j = 0; j < 64; j++) {
            long long v = p[j];
            if (v < 0 || v >= NN) { ok = 0; break; }
        }
        g_is64 = ok;
    }
}

// histogram dst
__global__ void count_kernel(const void* ei) {
    int e = blockIdx.x * blockDim.x + threadIdx.x;
    if (e >= EE) return;
    int d;
    if (g_is64) {
        const long long* p = (const long long*)ei;
        d = (int)p[(size_t)EE + e];
    } else {
        const int* p = (const int*)ei;
        d = p[EE + e];
    }
    atomicAdd(&g_deg[d], 1);
}

// ---------------- 3-phase scan over (deg-1); also dinv ----------------------
__global__ void scan_block_kernel() {          // SCAN_BLOCKS x 1024
    int i = blockIdx.x * 1024 + threadIdx.x;
    int deg = (i < NN) ? g_deg[i] : 1;
    int v = deg - 1;
    if (i < NN) g_dinv[i] = rsqrtf((float)deg);
    int lane = threadIdx.x & 31;
    int wid  = threadIdx.x >> 5;
    int x = v;
#pragma unroll
    for (int o = 1; o < 32; o <<= 1) {
        int y = __shfl_up_sync(0xffffffffu, x, o);
        if (lane >= o) x += y;
    }
    __shared__ int ws[32];
    if (lane == 31) ws[wid] = x;
    __syncthreads();
    if (wid == 0) {
        int w = ws[lane];
#pragma unroll
        for (int o = 1; o < 32; o <<= 1) {
            int y = __shfl_up_sync(0xffffffffu, w, o);
            if (lane >= o) w += y;
        }
        ws[lane] = w;
    }
    __syncthreads();
    int incl = x + (wid > 0 ? ws[wid - 1] : 0);
    if (i < NN) g_offs[i] = incl - v;          // block-local exclusive
    if (threadIdx.x == 1023) g_bsum[blockIdx.x] = incl;  // block total
}

__global__ void scan_sums_kernel() {           // 1 block x 64
    int lane = threadIdx.x & 31;
    int wid  = threadIdx.x >> 5;
    int v = (threadIdx.x < SCAN_BLOCKS) ? g_bsum[threadIdx.x] : 0;
    int x = v;
#pragma unroll
    for (int o = 1; o < 32; o <<= 1) {
        int y = __shfl_up_sync(0xffffffffu, x, o);
        if (lane >= o) x += y;
    }
    __shared__ int ws[2];
    if (lane == 31) ws[wid] = x;
    __syncthreads();
    int incl = x + (wid > 0 ? ws[0] : 0);
    if (threadIdx.x < SCAN_BLOCKS) g_bsumx[threadIdx.x] = incl - v; // exclusive
    if (threadIdx.x == 63) g_offs[NN] = incl;  // grand total (E)
}

__global__ void scan_add_kernel() {            // SCAN_BLOCKS x 1024
    int i = blockIdx.x * 1024 + threadIdx.x;
    if (i >= NN) return;
    int e = g_offs[i] + g_bsumx[blockIdx.x];
    g_offs[i] = e;
    g_cursor[i] = e;
}

// ---------------- SGEMM1 (tf32 tensor cores): h1 = relu(x@W1+b1) ------------
// R13 proven form: BK=32 single-buffer, cvt.rna at smem fill.
#define AS_STRIDE 40
#define BS_STRIDE 132

__global__ void __launch_bounds__(256, 2)
sgemm1_tc_kernel(const float* __restrict__ A,
                 const float* __restrict__ B,
                 const float* __restrict__ bias) {
    __shared__ float As[128 * AS_STRIDE];
    __shared__ float Bs[32 * BS_STRIDE];
    int tid  = threadIdx.x;
    int warp = tid >> 5;
    int lane = tid & 31;
    int g = lane >> 2;
    int t = lane & 3;
    int wm = (warp & 3) * 32;
    int wn = (warp >> 2) * 64;
    int bm = blockIdx.y * 128;
    int bn = blockIdx.x * 128;

    float c[2][8][4];
#pragma unroll
    for (int mt = 0; mt < 2; mt++)
#pragma unroll
        for (int nt = 0; nt < 8; nt++)
#pragma unroll
            for (int i = 0; i < 4; i++) c[mt][nt][i] = 0.f;

    for (int k0 = 0; k0 < HD; k0 += 32) {
#pragma unroll
        for (int i = 0; i < 4; i++) {
            int idx = tid + i * 256;
            int row = idx >> 3;
            int f   = idx & 7;
            float4 v;
            if (bm + row < NN)
                v = *(const float4*)&A[(size_t)(bm + row) * HD + k0 + f * 4];
            else
                v = make_float4(0.f, 0.f, 0.f, 0.f);
            v.x = __uint_as_float(tf32_bits(v.x));
            v.y = __uint_as_float(tf32_bits(v.y));
            v.z = __uint_as_float(tf32_bits(v.z));
            v.w = __uint_as_float(tf32_bits(v.w));
            *(float4*)&As[row * AS_STRIDE + f * 4] = v;
        }
#pragma unroll
        for (int i = 0; i < 4; i++) {
            int idx = tid + i * 256;
            int row = idx >> 5;
            int f   = idx & 31;
            float4 v = *(const float4*)&B[(size_t)(k0 + row) * 256 + bn + f * 4];
            v.x = __uint_as_float(tf32_bits(v.x));
            v.y = __uint_as_float(tf32_bits(v.y));
            v.z = __uint_as_float(tf32_bits(v.z));
            v.w = __uint_as_float(tf32_bits(v.w));
            *(float4*)&Bs[row * BS_STRIDE + f * 4] = v;
        }
        __syncthreads();

#pragma unroll
        for (int kk = 0; kk < 32; kk += 8) {
            unsigned a[2][4];
#pragma unroll
            for (int mt = 0; mt < 2; mt++) {
                int mrow = wm + mt * 16;
                a[mt][0] = __float_as_uint(As[(mrow + g)     * AS_STRIDE + kk + t]);
                a[mt][1] = __float_as_uint(As[(mrow + g + 8) * AS_STRIDE + kk + t]);
                a[mt][2] = __float_as_uint(As[(mrow + g)     * AS_STRIDE + kk + t + 4]);
                a[mt][3] = __float_as_uint(As[(mrow + g + 8) * AS_STRIDE + kk + t + 4]);
            }
            unsigned b[8][2];
#pragma unroll
            for (int nt = 0; nt < 8; nt++) {
                int ncol = wn + nt * 8;
                b[nt][0] = __float_as_uint(Bs[(kk + t)     * BS_STRIDE + ncol + g]);
                b[nt][1] = __float_as_uint(Bs[(kk + t + 4) * BS_STRIDE + ncol + g]);
            }
#pragma unroll
            for (int mt = 0; mt < 2; mt++)
#pragma unroll
                for (int nt = 0; nt < 8; nt++) {
                    asm volatile(
                        "mma.sync.aligned.m16n8k8.row.col.f32.tf32.tf32.f32 "
                        "{%0,%1,%2,%3}, {%4,%5,%6,%7}, {%8,%9}, {%0,%1,%2,%3};"
                        : "+f"(c[mt][nt][0]), "+f"(c[mt][nt][1]),
                          "+f"(c[mt][nt][2]), "+f"(c[mt][nt][3])
                        : "r"(a[mt][0]), "r"(a[mt][1]), "r"(a[mt][2]), "r"(a[mt][3]),
                          "r"(b[nt][0]), "r"(b[nt][1]));
                }
        }
        __syncthreads();
    }

#pragma unroll
    for (int mt = 0; mt < 2; mt++) {
        int row0 = bm + wm + mt * 16 + g;
        int row1 = row0 + 8;
#pragma unroll
        for (int nt = 0; nt < 8; nt++) {
            int col = bn + wn + nt * 8 + 2 * t;
            float bsv0 = bias[col];
            float bsv1 = bias[col + 1];
            if (row0 < NN) {
                float v0 = c[mt][nt][0] + bsv0;
                float v1 = c[mt][nt][1] + bsv1;
                g_h1[(size_t)row0 * HD + col]     = v0 > 0.f ? v0 : 0.f;
                g_h1[(size_t)row0 * HD + col + 1] = v1 > 0.f ? v1 : 0.f;
            }
            if (row1 < NN) {
                float v2 = c[mt][nt][2] + bsv0;
                float v3 = c[mt][nt][3] + bsv1;
                g_h1[(size_t)row1 * HD + col]     = v2 > 0.f ? v2 : 0.f;
                g_h1[(size_t)row1 * HD + col + 1] = v3 > 0.f ? v3 : 0.f;
            }
        }
    }
}

// ---------------- scatter into CSR straight from edge_index -----------------
__global__ void scatter_kernel(const void* ei) {
    int e = blockIdx.x * blockDim.x + threadIdx.x;
    if (e >= EE) return;
    int s, d;
    if (g_is64) {
        const long long* p = (const long long*)ei;
        s = (int)p[e];
        d = (int)p[(size_t)EE + e];
    } else {
        const int* p = (const int*)ei;
        s = p[e];
        d = p[EE + e];
    }
    int pos = atomicAdd(&g_cursor[d], 1);
    float w = g_dinv[s] * g_dinv[d];
    g_cw[pos] = make_int2(s, __float_as_int(w));
}

// ---------------- SGEMM2 (tf32 tensor cores) --------------------------------
#define A2_STRIDE 40
#define B2_STRIDE 52

__global__ void __launch_bounds__(256, 2)
sgemm2_tc_kernel(const float* __restrict__ B,     // W2 [256,48]
                 const float* __restrict__ bias,  // b2 [48]
                 const float* __restrict__ temp) {
    __shared__ float As[128 * A2_STRIDE];
    __shared__ float Bs[32 * B2_STRIDE];
    int tid  = threadIdx.x;
    int warp = tid >> 5;
    int lane = tid & 31;
    int g = lane >> 2;
    int t = lane & 3;
    int wm = warp * 16;
    int bm = blockIdx.x * 128;

    float c[6][4];
#pragma unroll
    for (int nt = 0; nt < 6; nt++)
#pragma unroll
        for (int i = 0; i < 4; i++) c[nt][i] = 0.f;

    for (int k0 = 0; k0 < HD; k0 += 32) {
#pragma unroll
        for (int i = 0; i < 4; i++) {
            int idx = tid + i * 256;
            int row = idx >> 3;
            int f   = idx & 7;
            float4 v;
            if (bm + row < NN)
                v = *(const float4*)&g_h1[(size_t)(bm + row) * HD + k0 + f * 4];
            else
                v = make_float4(0.f, 0.f, 0.f, 0.f);
            v.x = __uint_as_float(tf32_bits(v.x));
            v.y = __uint_as_float(tf32_bits(v.y));
            v.z = __uint_as_float(tf32_bits(v.z));
            v.w = __uint_as_float(tf32_bits(v.w));
            *(float4*)&As[row * A2_STRIDE + f * 4] = v;
        }
        for (int idx = tid; idx < 384; idx += 256) {
            int row = idx / 12;
            int f   = idx - row * 12;
            float4 v = *(const float4*)&B[(size_t)(k0 + row) * 48 + f * 4];
            v.x = __uint_as_float(tf32_bits(v.x));
            v.y = __uint_as_float(tf32_bits(v.y));
            v.z = __uint_as_float(tf32_bits(v.z));
            v.w = __uint_as_float(tf32_bits(v.w));
            *(float4*)&Bs[row * B2_STRIDE + f * 4] = v;
        }
        __syncthreads();

#pragma unroll
        for (int kk = 0; kk < 32; kk += 8) {
            unsigned a[4];
            a[0] = __float_as_uint(As[(wm + g)     * A2_STRIDE + kk + t]);
            a[1] = __float_as_uint(As[(wm + g + 8) * A2_STRIDE + kk + t]);
            a[2] = __float_as_uint(As[(wm + g)     * A2_STRIDE + kk + t + 4]);
            a[3] = __float_as_uint(As[(wm + g + 8) * A2_STRIDE + kk + t + 4]);
            unsigned b[6][2];
#pragma unroll
            for (int nt = 0; nt < 6; nt++) {
                int ncol = nt * 8;
                b[nt][0] = __float_as_uint(Bs[(kk + t)     * B2_STRIDE + ncol + g]);
                b[nt][1] = __float_as_uint(Bs[(kk + t + 4) * B2_STRIDE + ncol + g]);
            }
#pragma unroll
            for (int nt = 0; nt < 6; nt++) {
                asm volatile(
                    "mma.sync.aligned.m16n8k8.row.col.f32.tf32.tf32.f32 "
                    "{%0,%1,%2,%3}, {%4,%5,%6,%7}, {%8,%9}, {%0,%1,%2,%3};"
                    : "+f"(c[nt][0]), "+f"(c[nt][1]),
                      "+f"(c[nt][2]), "+f"(c[nt][3])
                    : "r"(a[0]), "r"(a[1]), "r"(a[2]), "r"(a[3]),
                      "r"(b[nt][0]), "r"(b[nt][1]));
            }
        }
        __syncthreads();
    }

    float t0 = temp[0];
    int row0 = bm + wm + g;
    int row1 = row0 + 8;
#pragma unroll
    for (int nt = 0; nt < 6; nt++) {
        int col = nt * 8 + 2 * t;
        float bs0 = bias[col];
        float bs1 = bias[col + 1];
        if (row0 < NN) {
            float v0 = c[nt][0] + bs0;
            float v1 = c[nt][1] + bs1;
            size_t o = (size_t)row0 * FD + col;
            g_hk0h[o]     = __float2half(v0);
            g_hk0h[o + 1] = __float2half(v1);
            g_hidden[o]     = t0 * v0;
            g_hidden[o + 1] = t0 * v1;
        }
        if (row1 < NN) {
            float v2 = c[nt][2] + bs0;
            float v3 = c[nt][3] + bs1;
            size_t o = (size_t)row1 * FD + col;
            g_hk0h[o]     = __float2half(v2);
            g_hk0h[o + 1] = __float2half(v3);
            g_hidden[o]     = t0 * v2;
            g_hidden[o + 1] = t0 * v3;
        }
    }
}

// ---------------- SpMM hop: smem-staged edge metadata -----------------------
// 384 threads = 32 nodes x 12. Block's CSR range is contiguous; stage it into
// smem once (coalesced, 1x traffic) instead of every thread re-reading g_cw
// (12x traffic). Gathers keep 8-wide independent-load structure.
#define SPMM_EDGE(ci, vi)                                                     \
    do {                                                                      \
        float w_ = __int_as_float((ci).y);                                    \
        float2 f_;                                                            \
        f_ = __half22float2(*(__half2*)&(vi).x); a0 += w_ * f_.x; a1 += w_ * f_.y; \
        f_ = __half22float2(*(__half2*)&(vi).y); a2 += w_ * f_.x; a3 += w_ * f_.y; \
    } while (0)

__global__ void __launch_bounds__(SPMM_THREADS)
spmm_kernel(const float* __restrict__ temp, int k, int parity, int store_next) {
    __shared__ int2 s_cw[SPMM_CHUNK];
    const __half* curh = parity ? g_hk1h : g_hk0h;
    __half*       nxth = parity ? g_hk0h : g_hk1h;
    int tid = threadIdx.x;
    int nib = tid / 12;                 // node in block 0..31
    int q   = tid - nib * 12;
    int d0  = blockIdx.x * SPMM_NODES;
    int d   = d0 + nib;
    bool active = (d < NN);
    const uint2* __restrict__ curv = (const uint2*)curh;

    int blk_e0 = g_offs[d0];
    int blk_e1 = g_offs[min(d0 + SPMM_NODES, NN)];
    int e0 = active ? g_offs[d]     : 0;
    int e1 = active ? g_offs[d + 1] : 0;

    float a0 = 0.f, a1 = 0.f, a2 = 0.f, a3 = 0.f;

    for (int base = blk_e0; base < blk_e1; base += SPMM_CHUNK) {
        int cnt = min(SPMM_CHUNK, blk_e1 - base);
        for (int i = tid; i < cnt; i += SPMM_THREADS)
            s_cw[i] = g_cw[base + i];
        __syncthreads();

        int lo = max(e0, base) - base;
        int hi = min(e1, base + cnt) - base;
        int e = lo;
        for (; e + 8 <= hi; e += 8) {
            int2 c0 = s_cw[e + 0];
            int2 c1 = s_cw[e + 1];
            int2 c2 = s_cw[e + 2];
            int2 c3 = s_cw[e + 3];
            int2 c4 = s_cw[e + 4];
            int2 c5 = s_cw[e + 5];
            int2 c6 = s_cw[e + 6];
            int2 c7 = s_cw[e + 7];
            uint2 v0 = __ldg(&curv[c0.x * 12 + q]);
            uint2 v1 = __ldg(&curv[c1.x * 12 + q]);
            uint2 v2 = __ldg(&curv[c2.x * 12 + q]);
            uint2 v3 = __ldg(&curv[c3.x * 12 + q]);
            uint2 v4 = __ldg(&curv[c4.x * 12 + q]);
            uint2 v5 = __ldg(&curv[c5.x * 12 + q]);
            uint2 v6 = __ldg(&curv[c6.x * 12 + q]);
            uint2 v7 = __ldg(&curv[c7.x * 12 + q]);
            SPMM_EDGE(c0, v0); SPMM_EDGE(c1, v1);
            SPMM_EDGE(c2, v2); SPMM_EDGE(c3, v3);
            SPMM_EDGE(c4, v4); SPMM_EDGE(c5, v5);
            SPMM_EDGE(c6, v6); SPMM_EDGE(c7, v7);
        }
        for (; e + 2 <= hi; e += 2) {
            int2 c0 = s_cw[e + 0];
            int2 c1 = s_cw[e + 1];
            uint2 v0 = __ldg(&curv[c0.x * 12 + q]);
            uint2 v1 = __ldg(&curv[c1.x * 12 + q]);
            SPMM_EDGE(c0, v0); SPMM_EDGE(c1, v1);
        }
        if (e < hi) {
            int2 c0 = s_cw[e];
            uint2 v0 = __ldg(&curv[c0.x * 12 + q]);
            SPMM_EDGE(c0, v0);
        }
        __syncthreads();
    }

    if (!active) return;

    // self loop
    {
        float di = g_dinv[d];
        float sw = di * di;
        uint2 v0 = __ldg(&curv[d * 12 + q]);
        float2 f;
        f = __half22float2(*(__half2*)&v0.x); a0 += sw * f.x; a1 += sw * f.y;
        f = __half22float2(*(__half2*)&v0.y); a2 += sw * f.x; a3 += sw * f.y;
    }

    float tk = temp[k];
    int o = d * 12 + q;
    if (store_next) {
        uint2 packed;
        __half2 h0 = __floats2half2_rn(a0, a1);
        __half2 h1 = __floats2half2_rn(a2, a3);
        packed.x = *(unsigned*)&h0;
        packed.y = *(unsigned*)&h1;
        ((uint2*)nxth)[o] = packed;
    }
    float4* hidv = (float4*)g_hidden;
    float4 hv = hidv[o];
    hv.x += tk * a0; hv.y += tk * a1;
    hv.z += tk * a2; hv.w += tk * a3;
    hidv[o] = hv;
}

// ---------------- log_softmax over 48 cols, warp per row --------------------
__global__ void logsoftmax_kernel(float* __restrict__ out) {
    int warp = (blockIdx.x * blockDim.x + threadIdx.x) >> 5;
    int lane = threadIdx.x & 31;
    if (warp >= NN) return;
    size_t base = (size_t)warp * FD;
    float v0 = g_hidden[base + lane];
    float v1 = (lane < 16) ? g_hidden[base + 32 + lane] : -INFINITY;
    float m = fmaxf(v0, v1);
#pragma unroll
    for (int off = 16; off > 0; off >>= 1)
        m = fmaxf(m, __shfl_xor_sync(0xffffffffu, m, off));
    float s = expf(v0 - m) + ((lane < 16) ? expf(v1 - m) : 0.f);
#pragma unroll
    for (int off = 16; off > 0; off >>= 1)
        s += __shfl_xor_sync(0xffffffffu, s, off);
    float l = m + logf(s);
    out[base + lane] = v0 - l;
    if (lane < 16) out[base + 32 + lane] = v1 - l;
}

// ---------------- launch (fork CSR build onto side stream) ------------------
extern "C" void kernel_launch(void* const* d_in, const int* in_sizes, int n_in,
                              void* d_out, int out_size) {
    const float* x    = (const float*)d_in[0];
    const void*  ei   = d_in[1];
    const float* W1   = (const float*)d_in[2];
    const float* b1   = (const float*)d_in[3];
    const float* W2   = (const float*)d_in[4];
    const float* b2   = (const float*)d_in[5];
    const float* temp = (const float*)d_in[6];
    float* out = (float*)d_out;

    static cudaStream_t s2 = nullptr;
    static cudaEvent_t ev_fork = nullptr, ev_join = nullptr;
    if (s2 == nullptr) {
        cudaStreamCreateWithFlags(&s2, cudaStreamNonBlocking);
        cudaEventCreateWithFlags(&ev_fork, cudaEventDisableTiming);
        cudaEventCreateWithFlags(&ev_join, cudaEventDisableTiming);
    }

    // fork: side stream builds CSR while main stream runs the MLP GEMMs
    cudaEventRecord(ev_fork, 0);
    cudaStreamWaitEvent(s2, ev_fork, 0);

    detect_init_kernel<<<(NN + 255) / 256, 256, 0, s2>>>(ei);
    count_kernel<<<(EE + 255) / 256, 256, 0, s2>>>(ei);
    scan_block_kernel<<<SCAN_BLOCKS, 1024, 0, s2>>>();
    scan_sums_kernel<<<1, 64, 0, s2>>>();
    scan_add_kernel<<<SCAN_BLOCKS, 1024, 0, s2>>>();
    scatter_kernel<<<(EE + 255) / 256, 256, 0, s2>>>(ei);
    cudaEventRecord(ev_join, s2);

    dim3 g1(2, (NN + 127) / 128);
    sgemm1_tc_kernel<<<g1, 256>>>(x, W1, b1);
    sgemm2_tc_kernel<<<(NN + 127) / 128, 256>>>(W2, b2, temp);

    // join: spmm needs CSR (side) and hk0/hidden (main)
    cudaStreamWaitEvent(0, ev_join, 0);

    int spmm_blocks = (NN + SPMM_NODES - 1) / SPMM_NODES;
    for (int k = 1; k <= KHOP; k++) {
        spmm_kernel<<<spmm_blocks, SPMM_THREADS>>>(temp, k, (k - 1) & 1, k < KHOP);
    }
    logsoftmax_kernel<<<(NN * 32 + 255) / 256, 256>>>(out);
}